// round 6
// baseline (speedup 1.0000x reference)
#include <cuda_runtime.h>
#include <math.h>

#define BB 128
#define TT 1024
#define DD 43
#define HH 256
#define G4 1024

// ---- static device scratch (allocation-free) ----
__device__ float g_xg[(size_t)TT * BB * G4];   // [t][b][g]  512 MB
__device__ float g_hs[(size_t)BB * TT * HH];   // [b][t][k]  128 MB
__device__ float g_a1[(size_t)BB * TT * HH];   // [tok][k]   128 MB
__device__ int   g_bar[16];                    // per batch-group barrier counters

__device__ __forceinline__ int ld_acquire(const int* p) {
    int v;
    asm volatile("ld.acquire.gpu.global.b32 %0, [%1];" : "=r"(v) : "l"(p));
    return v;
}

__device__ __forceinline__ float sigmoidf_(float x) {
    return 1.0f / (1.0f + __expf(-x));
}

// ---------------------------------------------------------------------------
// init: zero barrier counters (must run every launch/replay)
// ---------------------------------------------------------------------------
__global__ void k_init() {
    if (threadIdx.x < 16) g_bar[threadIdx.x] = 0;
}

// ---------------------------------------------------------------------------
// Kernel A: xg[t][b][g] = xin[b,t,:] . W_ih[g,:] + b_ih[g] + b_hh[g]
//   xin[b,t,d] = x[b,t,d] (d<35) ; x[b,t-1,d] (35<=d<43, t>0) ; 0 (t==0)
// grid (4 gate-tiles, 32 t-tiles, 128 b), 256 threads (one per gate in tile)
// ---------------------------------------------------------------------------
__global__ void __launch_bounds__(256) kA(const float* __restrict__ x,
                                          const float* __restrict__ Wih,
                                          const float* __restrict__ bih,
                                          const float* __restrict__ bhh) {
    __shared__ float xin[32 * 44];
    const int tid = threadIdx.x;
    const int g0  = blockIdx.x * 256;
    const int t0  = blockIdx.y * 32;
    const int b   = blockIdx.z;

    for (int e = tid; e < 32 * 44; e += 256) {
        int tt = e / 44, d = e % 44;
        int t = t0 + tt;
        float v = 0.0f;
        if (d < 35)      v = x[((size_t)b * TT + t) * DD + d];
        else if (d < 43) { if (t > 0) v = x[((size_t)b * TT + t - 1) * DD + d]; }
        xin[e] = v;
    }

    const int g = g0 + tid;
    float w[44];
#pragma unroll
    for (int d = 0; d < 43; d++) w[d] = Wih[g * DD + d];
    w[43] = 0.0f;
    const float bias = bih[g] + bhh[g];
    __syncthreads();

#pragma unroll 4
    for (int tt = 0; tt < 32; tt++) {
        const float* xr = &xin[tt * 44];
        float acc = bias;
#pragma unroll
        for (int d = 0; d < 44; d++) acc += w[d] * xr[d];
        g_xg[((size_t)(t0 + tt) * BB + b) * G4 + g] = acc;
    }
}

// ---------------------------------------------------------------------------
// Kernel B: persistent LSTM. 128 CTAs = 16 batch-groups x 8 hidden-slices.
// CTA holds its 128x256 W_hh slice in smem (stride 260). h exchanged through
// g_hs in L2; per-batch-group software barrier each step.
// ---------------------------------------------------------------------------
#define WSTR 260
#define SMEM_B ((128 * WSTR + 256 * 8 + 128 * 9) * 4)

__global__ void __launch_bounds__(256, 1) kB(const float* __restrict__ Whh) {
    extern __shared__ float sm[];
    float* Wsh = sm;                    // [128][260]
    float* hsh = Wsh + 128 * WSTR;      // [256][8]  (k-major, batch minor)
    float* gsh = hsh + 256 * 8;         // [128][9]  raw gates

    const int tid = threadIdx.x;
    const int cta = blockIdx.x;
    const int bg  = cta >> 3;           // batch group 0..15
    const int hsl = cta & 7;            // hidden slice 0..7
    const int b0  = bg * 8;

    // load W_hh slice: local row r -> global row (r>>5)*256 + hsl*32 + (r&31)
    for (int e = tid; e < 128 * 256; e += 256) {
        int r = e >> 8, k = e & 255;
        int R = ((r >> 5) << 8) + hsl * 32 + (r & 31);
        Wsh[r * WSTR + k] = Whh[R * 256 + k];
    }

    // compute-thread mapping
    const int r  = tid >> 1;            // gate row 0..127
    const int bh = tid & 1;             // batch half (4 batches each)
    const int R  = ((r >> 5) << 8) + hsl * 32 + (r & 31);
    // update-thread mapping
    const int ub = tid >> 5;            // batch 0..7
    const int uk = tid & 31;            // local hidden 0..31
    float c = 0.0f;

    __syncthreads();

    for (int t = 0; t < TT; t++) {
        // ---- stage h(t-1) into smem ----
        if (t == 0) {
            for (int e = tid; e < 256 * 8; e += 256) hsh[e] = 0.0f;
        } else {
            int gk = tid >> 3, bb = tid & 7;
            const float* src = &g_hs[(((size_t)(b0 + bb)) * TT + (t - 1)) * HH + gk * 8];
#pragma unroll
            for (int i = 0; i < 8; i++)
                hsh[(gk * 8 + i) * 8 + bb] = __ldcg(&src[i]);
        }
        __syncthreads();

        // ---- gates = xg + W.h ----
        {
            const float* xgp = &g_xg[((size_t)t * BB + b0 + bh * 4) * G4 + R];
            float a0 = xgp[0], a1 = xgp[G4], a2 = xgp[2 * G4], a3 = xgp[3 * G4];
            const float4* wp = (const float4*)&Wsh[r * WSTR];
            const float4* hp = (const float4*)&hsh[bh * 4];   // hp[2k] = h[k][bh*4..+3]
#pragma unroll 8
            for (int k4 = 0; k4 < 64; k4++) {
                float4 w4 = wp[k4];
                float4 h0 = hp[(4 * k4 + 0) * 2];
                float4 h1 = hp[(4 * k4 + 1) * 2];
                float4 h2 = hp[(4 * k4 + 2) * 2];
                float4 h3 = hp[(4 * k4 + 3) * 2];
                a0 += w4.x * h0.x + w4.y * h1.x + w4.z * h2.x + w4.w * h3.x;
                a1 += w4.x * h0.y + w4.y * h1.y + w4.z * h2.y + w4.w * h3.y;
                a2 += w4.x * h0.z + w4.y * h1.z + w4.z * h2.z + w4.w * h3.z;
                a3 += w4.x * h0.w + w4.y * h1.w + w4.z * h2.w + w4.w * h3.w;
            }
            float* gp = &gsh[r * 9 + bh * 4];
            gp[0] = a0; gp[1] = a1; gp[2] = a2; gp[3] = a3;
        }
        __syncthreads();

        // ---- pointwise LSTM update (thread owns (uk, ub), c in register) ----
        {
            float gi = sigmoidf_(gsh[(uk)        * 9 + ub]);
            float gf = sigmoidf_(gsh[(32 + uk)   * 9 + ub]);
            float gg = tanhf(    gsh[(64 + uk)   * 9 + ub]);
            float go = sigmoidf_(gsh[(96 + uk)   * 9 + ub]);
            c = gf * c + gi * gg;
            float h = go * tanhf(c);
            g_hs[(((size_t)(b0 + ub)) * TT + t) * HH + hsl * 32 + uk] = h;
        }
        __threadfence();
        __syncthreads();
        if (tid == 0) {
            atomicAdd(&g_bar[bg], 1);
            const int target = 8 * (t + 1);
            while (ld_acquire(&g_bar[bg]) < target) { }
        }
        __syncthreads();
    }
}

// ---------------------------------------------------------------------------
// Kernel C1: a1 = relu(hs @ W_afc1^T + b).  Block: 32 tokens x 256 outputs.
// ---------------------------------------------------------------------------
#define SMEM_C1 ((32 * 256 + 256 * 68) * 4)

__global__ void __launch_bounds__(256) kC1(const float* __restrict__ Wa,
                                           const float* __restrict__ ba) {
    extern __shared__ float sm[];
    float* hsh = sm;               // [32][256]
    float* Ws  = sm + 32 * 256;    // [256][68] current K-chunk

    const int tid  = threadIdx.x;
    const int tok0 = blockIdx.x * 32;

    for (int e = tid; e < 32 * 256; e += 256)
        hsh[e] = g_hs[(size_t)tok0 * 256 + e];

    float acc[32];
    const float bias = ba[tid];
#pragma unroll
    for (int i = 0; i < 32; i++) acc[i] = bias;

    for (int kc = 0; kc < 4; kc++) {
        __syncthreads();
        for (int e = tid; e < 256 * 64; e += 256) {
            int j = e >> 6, kk = e & 63;
            Ws[j * 68 + kk] = Wa[j * 256 + kc * 64 + kk];
        }
        __syncthreads();
        const float4* wp = (const float4*)&Ws[tid * 68];
#pragma unroll
        for (int q = 0; q < 16; q++) {
            float4 w4 = wp[q];
            const int kbase = kc * 64 + q * 4;
#pragma unroll 8
            for (int tt = 0; tt < 32; tt++) {
                float4 h = *(const float4*)&hsh[tt * 256 + kbase];
                acc[tt] += w4.x * h.x + w4.y * h.y + w4.z * h.z + w4.w * h.w;
            }
        }
    }
#pragma unroll
    for (int tt = 0; tt < 32; tt++)
        g_a1[((size_t)(tok0 + tt)) * 256 + tid] = fmaxf(acc[tt], 0.0f);
}

// ---------------------------------------------------------------------------
// Kernel C2: cont / bin / act heads. Block: 32 tokens, all weights in smem.
// out layout: [cont 128*1024*50][bin 128*1024*10][act 128*1024*8]
// ---------------------------------------------------------------------------
#define CONT_BASE 0
#define BIN_BASE  (128 * 1024 * 50)
#define ACT_BASE  (BIN_BASE + 128 * 1024 * 10)
#define SMEM_C2 ((32 * 268 + 32 * 256 + 50 * 268 + 10 * 268 + 8 * 256 + 68) * 4)

__global__ void __launch_bounds__(256) kC2(const float* __restrict__ x,
                                           const float* __restrict__ Wao,
                                           const float* __restrict__ bao,
                                           const float* __restrict__ Wc,
                                           const float* __restrict__ bc,
                                           const float* __restrict__ Wb,
                                           const float* __restrict__ bb,
                                           float* __restrict__ out) {
    extern __shared__ float sm[];
    float* pred = sm;                   // [32][268]  (h | cur)
    float* a1s  = pred + 32 * 268;      // [32][256]
    float* Wcs  = a1s  + 32 * 256;      // [50][268]
    float* Wbs  = Wcs  + 50 * 268;      // [10][268]
    float* Was  = Wbs  + 10 * 268;      // [8][256]
    float* bcs  = Was  + 8 * 256;       // 50
    float* bbs  = bcs + 50;             // 10
    float* bas  = bbs + 10;             // 8

    const int tid  = threadIdx.x;
    const int tok0 = blockIdx.x * 32;

    for (int e = tid; e < 32 * 256; e += 256) {
        int tt = e >> 8, k = e & 255;
        pred[tt * 268 + k] = g_hs[(size_t)tok0 * 256 + e];
        a1s[e]             = g_a1[(size_t)tok0 * 256 + e];
    }
    if (tid < 32 * 8) {
        int tt = tid >> 3, j = tid & 7;
        pred[tt * 268 + 256 + j] = x[((size_t)(tok0 + tt)) * DD + 35 + j];
    }
    for (int e = tid; e < 50 * 264; e += 256) {
        int o = e / 264, d = e % 264;
        Wcs[o * 268 + d] = Wc[e];
    }
    for (int e = tid; e < 10 * 264; e += 256) {
        int o = e / 264, d = e % 264;
        Wbs[o * 268 + d] = Wb[e];
    }
    for (int e = tid; e < 8 * 256; e += 256) Was[e] = Wao[e];
    if (tid < 50) bcs[tid] = bc[tid];
    if (tid < 10) bbs[tid] = bb[tid];
    if (tid < 8)  bas[tid] = bao[tid];
    __syncthreads();

    for (int idx = tid; idx < 32 * 68; idx += 256) {
        const int tt   = idx / 68;
        const int o    = idx % 68;
        const int gtok = tok0 + tt;
        if (o < 50) {
            float acc = bcs[o];
            const float4* wp = (const float4*)&Wcs[o * 268];
            const float4* pp = (const float4*)&pred[tt * 268];
#pragma unroll 11
            for (int q = 0; q < 66; q++) {
                float4 w = wp[q], p = pp[q];
                acc += w.x * p.x + w.y * p.y + w.z * p.z + w.w * p.w;
            }
            out[CONT_BASE + (size_t)gtok * 50 + o] = acc;
        } else if (o < 60) {
            const int o2 = o - 50;
            float acc = bbs[o2];
            const float4* wp = (const float4*)&Wbs[o2 * 268];
            const float4* pp = (const float4*)&pred[tt * 268];
#pragma unroll 11
            for (int q = 0; q < 66; q++) {
                float4 w = wp[q], p = pp[q];
                acc += w.x * p.x + w.y * p.y + w.z * p.z + w.w * p.w;
            }
            out[BIN_BASE + (size_t)gtok * 10 + o2] = 1.0f / (1.0f + __expf(-acc));
        } else {
            const int o3 = o - 60;
            float acc = bas[o3];
            const float4* wp = (const float4*)&Was[o3 * 256];
            const float4* pp = (const float4*)&a1s[tt * 256];
#pragma unroll 16
            for (int q = 0; q < 64; q++) {
                float4 w = wp[q], p = pp[q];
                acc += w.x * p.x + w.y * p.y + w.z * p.z + w.w * p.w;
            }
            out[ACT_BASE + (size_t)gtok * 8 + o3] = acc;
        }
    }
}

// ---------------------------------------------------------------------------
extern "C" void kernel_launch(void* const* d_in, const int* in_sizes, int n_in,
                              void* d_out, int out_size) {
    const float* x    = (const float*)d_in[0];
    const float* Wih  = (const float*)d_in[1];
    const float* Whh  = (const float*)d_in[2];
    const float* bih  = (const float*)d_in[3];
    const float* bhh  = (const float*)d_in[4];
    const float* Wafc = (const float*)d_in[5];
    const float* bafc = (const float*)d_in[6];
    const float* Wao  = (const float*)d_in[7];
    const float* bao  = (const float*)d_in[8];
    const float* Wc   = (const float*)d_in[9];
    const float* bc   = (const float*)d_in[10];
    const float* Wb   = (const float*)d_in[11];
    const float* bb   = (const float*)d_in[12];
    float* out = (float*)d_out;

    cudaFuncSetAttribute(kB,  cudaFuncAttributeMaxDynamicSharedMemorySize, SMEM_B);
    cudaFuncSetAttribute(kC1, cudaFuncAttributeMaxDynamicSharedMemorySize, SMEM_C1);
    cudaFuncSetAttribute(kC2, cudaFuncAttributeMaxDynamicSharedMemorySize, SMEM_C2);

    k_init<<<1, 32>>>();
    kA<<<dim3(4, 32, 128), 256>>>(x, Wih, bih, bhh);
    kB<<<128, 256, SMEM_B>>>(Whh);
    kC1<<<4096, 256, SMEM_C1>>>(Wafc, bafc);
    kC2<<<4096, 256, SMEM_C2>>>(x, Wao, bao, Wc, bc, Wb, bb, out);
}

// round 8
// speedup vs baseline: 1.0377x; 1.0377x over previous
#include <cuda_runtime.h>
#include <math.h>

#define BB 128
#define TT 1024
#define DD 43
#define HH 256
#define G4 1024

// ---- static device scratch (allocation-free) ----
__device__ float g_xg[(size_t)TT * BB * G4];   // [t][b][g]
__device__ float g_hs[(size_t)BB * TT * HH];   // [b][t][k]
__device__ float g_a1[(size_t)BB * TT * HH];   // [tok][k]
__device__ int   g_bar[16 * 64];               // padded: one counter per 256B

__device__ __forceinline__ int ld_acquire(const int* p) {
    int v;
    asm volatile("ld.acquire.gpu.global.b32 %0, [%1];" : "=r"(v) : "l"(p));
    return v;
}
__device__ __forceinline__ void red_release_add(int* p, int v) {
    asm volatile("red.release.gpu.global.add.s32 [%0], %1;" :: "l"(p), "r"(v) : "memory");
}
__device__ __forceinline__ float sigmoidf_(float x) {
    return 1.0f / (1.0f + __expf(-x));
}

#define PACK2(d, lo, hi) asm("mov.b64 %0, {%1, %2};" : "=l"(d) : "f"(lo), "f"(hi))
#define DUP2(d, s)       asm("mov.b64 %0, {%1, %1};" : "=l"(d) : "f"(s))
#define UNPACK2(lo, hi, s) asm("mov.b64 {%0, %1}, %2;" : "=f"(lo), "=f"(hi) : "l"(s))
#define FFMA2(acc, a, b) asm("fma.rn.f32x2 %0, %1, %2, %0;" : "+l"(acc) : "l"(a), "l"(b))

// ---------------------------------------------------------------------------
__global__ void k_init() {
    if (threadIdx.x < 16) g_bar[threadIdx.x * 64] = 0;
}

// ---------------------------------------------------------------------------
// Kernel A: xg[t][b][g] = xin[b,t,:] . W_ih[g,:] + b_ih[g] + b_hh[g]
// ---------------------------------------------------------------------------
__global__ void __launch_bounds__(256) kA(const float* __restrict__ x,
                                          const float* __restrict__ Wih,
                                          const float* __restrict__ bih,
                                          const float* __restrict__ bhh) {
    __shared__ float xin[32 * 44];
    const int tid = threadIdx.x;
    const int g0  = blockIdx.x * 256;
    const int t0  = blockIdx.y * 32;
    const int b   = blockIdx.z;

    for (int e = tid; e < 32 * 44; e += 256) {
        int tt = e / 44, d = e % 44;
        int t = t0 + tt;
        float v = 0.0f;
        if (d < 35)      v = x[((size_t)b * TT + t) * DD + d];
        else if (d < 43) { if (t > 0) v = x[((size_t)b * TT + t - 1) * DD + d]; }
        xin[e] = v;
    }

    const int g = g0 + tid;
    float w[44];
#pragma unroll
    for (int d = 0; d < 43; d++) w[d] = Wih[g * DD + d];
    w[43] = 0.0f;
    const float bias = bih[g] + bhh[g];
    __syncthreads();

#pragma unroll 4
    for (int tt = 0; tt < 32; tt++) {
        const float* xr = &xin[tt * 44];
        float acc = bias;
#pragma unroll
        for (int d = 0; d < 44; d++) acc += w[d] * xr[d];
        g_xg[((size_t)(t0 + tt) * BB + b) * G4 + g] = acc;
    }
}

// ---------------------------------------------------------------------------
// Kernel B: persistent LSTM. 128 CTAs = 16 batch-groups x 8 hidden-slices.
// f32x2 packed gate GEMM, padded release/acquire barrier, xg prefetch.
// ---------------------------------------------------------------------------
#define WSTR 260
#define SMEM_B ((128 * WSTR + 256 * 8 + 128 * 9) * 4)

__global__ void __launch_bounds__(256, 1) kB(const float* __restrict__ Whh) {
    extern __shared__ float sm[];
    float* Wsh = sm;                    // [128][260]
    float* hsh = Wsh + 128 * WSTR;      // [256][8]  (k-major, batch minor)
    float* gsh = hsh + 256 * 8;         // [128][9]  raw gates

    const int tid = threadIdx.x;
    const int cta = blockIdx.x;
    const int bg  = cta >> 3;           // batch group 0..15
    const int hsl = cta & 7;            // hidden slice 0..7
    const int b0  = bg * 8;

    // load W_hh slice: local row r -> global row (r>>5)*256 + hsl*32 + (r&31)
    for (int e = tid; e < 128 * 256; e += 256) {
        int r = e >> 8, k = e & 255;
        int R = ((r >> 5) << 8) + hsl * 32 + (r & 31);
        Wsh[r * WSTR + k] = Whh[R * 256 + k];
    }

    // compute-thread mapping
    const int r  = tid >> 1;            // gate row 0..127
    const int bh = tid & 1;             // batch half (4 batches each)
    const int R  = ((r >> 5) << 8) + hsl * 32 + (r & 31);
    // update-thread mapping
    const int ub = tid >> 5;            // batch 0..7
    const int uk = tid & 31;            // local hidden 0..31
    // stage-thread mapping
    const int gk = tid >> 3;            // k-octet 0..31
    const int sb = tid & 7;             // batch 0..7
    float c = 0.0f;

    int* barp = &g_bar[bg * 64];

    // prefetch xg for t=0
    float px0, px1, px2, px3;
    {
        const float* p = &g_xg[((size_t)b0 + bh * 4) * G4 + R];
        px0 = __ldcg(p); px1 = __ldcg(p + G4);
        px2 = __ldcg(p + 2 * G4); px3 = __ldcg(p + 3 * G4);
    }

    // h(-1) = 0
    for (int e = tid; e < 256 * 8; e += 256) hsh[e] = 0.0f;
    __syncthreads();

    for (int t = 0; t < TT; t++) {
        // ---- gates = xg + W.h  (packed f32x2, pairs over batches) ----
        {
            unsigned long long p01, p23;
            PACK2(p01, px0, px1);
            PACK2(p23, px2, px3);
            const float4* wp = (const float4*)&Wsh[r * WSTR];
            const ulonglong2* hq = (const ulonglong2*)hsh;   // hq[k*2+bh] = pairs
#pragma unroll 8
            for (int k4 = 0; k4 < 64; k4++) {
                float4 w4 = wp[k4];
                ulonglong2 hA = hq[(4 * k4 + 0) * 2 + bh];
                ulonglong2 hB = hq[(4 * k4 + 1) * 2 + bh];
                ulonglong2 hC = hq[(4 * k4 + 2) * 2 + bh];
                ulonglong2 hD = hq[(4 * k4 + 3) * 2 + bh];
                unsigned long long w2;
                DUP2(w2, w4.x);
                FFMA2(p01, w2, hA.x); FFMA2(p23, w2, hA.y);
                DUP2(w2, w4.y);
                FFMA2(p01, w2, hB.x); FFMA2(p23, w2, hB.y);
                DUP2(w2, w4.z);
                FFMA2(p01, w2, hC.x); FFMA2(p23, w2, hC.y);
                DUP2(w2, w4.w);
                FFMA2(p01, w2, hD.x); FFMA2(p23, w2, hD.y);
            }
            float a0, a1, a2, a3;
            UNPACK2(a0, a1, p01);
            UNPACK2(a2, a3, p23);
            float* gp = &gsh[r * 9 + bh * 4];
            gp[0] = a0; gp[1] = a1; gp[2] = a2; gp[3] = a3;
        }
        __syncthreads();

        // ---- pointwise LSTM update ----
        {
            float gi = sigmoidf_(gsh[(uk)      * 9 + ub]);
            float gf = sigmoidf_(gsh[(32 + uk) * 9 + ub]);
            float gg = tanhf(    gsh[(64 + uk) * 9 + ub]);
            float go = sigmoidf_(gsh[(96 + uk) * 9 + ub]);
            c = gf * c + gi * gg;
            float h = go * tanhf(c);
            g_hs[(((size_t)(b0 + ub)) * TT + t) * HH + hsl * 32 + uk] = h;
        }

        // ---- prefetch xg for next step (independent of barrier) ----
        {
            int tn = (t + 1 < TT) ? (t + 1) : t;
            const float* p = &g_xg[((size_t)tn * BB + b0 + bh * 4) * G4 + R];
            px0 = __ldcg(p); px1 = __ldcg(p + G4);
            px2 = __ldcg(p + 2 * G4); px3 = __ldcg(p + 3 * G4);
        }

        // ---- inter-CTA barrier: release-add, then one spinner ----
        __syncthreads();                       // all h STGs before release
        if (tid == 0) {
            red_release_add(barp, 1);
            const int target = 8 * (t + 1);
            while (ld_acquire(barp) < target) { }
        }
        __syncthreads();

        // ---- stage h(t) into smem for step t+1 ----
        if (t + 1 < TT) {
            const float4* src = (const float4*)
                &g_hs[(((size_t)(b0 + sb)) * TT + t) * HH + gk * 8];
            float4 v0 = __ldcg(src);
            float4 v1 = __ldcg(src + 1);
            float* dst = &hsh[(gk * 8) * 8 + sb];
            dst[0]  = v0.x; dst[8]  = v0.y; dst[16] = v0.z; dst[24] = v0.w;
            dst[32] = v1.x; dst[40] = v1.y; dst[48] = v1.z; dst[56] = v1.w;
        }
        __syncthreads();
    }
}

// ---------------------------------------------------------------------------
// Kernel C1: a1 = relu(hs @ W_afc1^T + b).  Block: 32 tokens x 256 outputs.
// ---------------------------------------------------------------------------
#define SMEM_C1 ((32 * 256 + 256 * 68) * 4)

__global__ void __launch_bounds__(256) kC1(const float* __restrict__ Wa,
                                           const float* __restrict__ ba) {
    extern __shared__ float sm[];
    float* hsh = sm;               // [32][256]
    float* Ws  = sm + 32 * 256;    // [256][68] current K-chunk

    const int tid  = threadIdx.x;
    const int tok0 = blockIdx.x * 32;

    for (int e = tid; e < 32 * 256; e += 256)
        hsh[e] = g_hs[(size_t)tok0 * 256 + e];

    float acc[32];
    const float bias = ba[tid];
#pragma unroll
    for (int i = 0; i < 32; i++) acc[i] = bias;

    for (int kc = 0; kc < 4; kc++) {
        __syncthreads();
        for (int e = tid; e < 256 * 64; e += 256) {
            int j = e >> 6, kk = e & 63;
            Ws[j * 68 + kk] = Wa[j * 256 + kc * 64 + kk];
        }
        __syncthreads();
        const float4* wp = (const float4*)&Ws[tid * 68];
#pragma unroll
        for (int q = 0; q < 16; q++) {
            float4 w4 = wp[q];
            const int kbase = kc * 64 + q * 4;
#pragma unroll 8
            for (int tt = 0; tt < 32; tt++) {
                float4 h = *(const float4*)&hsh[tt * 256 + kbase];
                acc[tt] += w4.x * h.x + w4.y * h.y + w4.z * h.z + w4.w * h.w;
            }
        }
    }
#pragma unroll
    for (int tt = 0; tt < 32; tt++)
        g_a1[((size_t)(tok0 + tt)) * 256 + tid] = fmaxf(acc[tt], 0.0f);
}

// ---------------------------------------------------------------------------
// Kernel C2: cont / bin / act heads.
// ---------------------------------------------------------------------------
#define CONT_BASE 0
#define BIN_BASE  (128 * 1024 * 50)
#define ACT_BASE  (BIN_BASE + 128 * 1024 * 10)
#define SMEM_C2 ((32 * 268 + 32 * 256 + 50 * 268 + 10 * 268 + 8 * 256 + 68) * 4)

__global__ void __launch_bounds__(256) kC2(const float* __restrict__ x,
                                           const float* __restrict__ Wao,
                                           const float* __restrict__ bao,
                                           const float* __restrict__ Wc,
                                           const float* __restrict__ bc,
                                           const float* __restrict__ Wb,
                                           const float* __restrict__ bb,
                                           float* __restrict__ out) {
    extern __shared__ float sm[];
    float* pred = sm;                   // [32][268]  (h | cur)
    float* a1s  = pred + 32 * 268;      // [32][256]
    float* Wcs  = a1s  + 32 * 256;      // [50][268]
    float* Wbs  = Wcs  + 50 * 268;      // [10][268]
    float* Was  = Wbs  + 10 * 268;      // [8][256]
    float* bcs  = Was  + 8 * 256;       // 50
    float* bbs  = bcs + 50;             // 10
    float* bas  = bbs + 10;             // 8

    const int tid  = threadIdx.x;
    const int tok0 = blockIdx.x * 32;

    for (int e = tid; e < 32 * 256; e += 256) {
        int tt = e >> 8, k = e & 255;
        pred[tt * 268 + k] = g_hs[(size_t)tok0 * 256 + e];
        a1s[e]             = g_a1[(size_t)tok0 * 256 + e];
    }
    if (tid < 32 * 8) {
        int tt = tid >> 3, j = tid & 7;
        pred[tt * 268 + 256 + j] = x[((size_t)(tok0 + tt)) * DD + 35 + j];
    }
    for (int e = tid; e < 50 * 264; e += 256) {
        int o = e / 264, d = e % 264;
        Wcs[o * 268 + d] = Wc[e];
    }
    for (int e = tid; e < 10 * 264; e += 256) {
        int o = e / 264, d = e % 264;
        Wbs[o * 268 + d] = Wb[e];
    }
    for (int e = tid; e < 8 * 256; e += 256) Was[e] = Wao[e];
    if (tid < 50) bcs[tid] = bc[tid];
    if (tid < 10) bbs[tid] = bb[tid];
    if (tid < 8)  bas[tid] = bao[tid];
    __syncthreads();

    for (int idx = tid; idx < 32 * 68; idx += 256) {
        const int tt   = idx / 68;
        const int o    = idx % 68;
        const int gtok = tok0 + tt;
        if (o < 50) {
            float acc = bcs[o];
            const float4* wp = (const float4*)&Wcs[o * 268];
            const float4* pp = (const float4*)&pred[tt * 268];
#pragma unroll 11
            for (int q = 0; q < 66; q++) {
                float4 w = wp[q], p = pp[q];
                acc += w.x * p.x + w.y * p.y + w.z * p.z + w.w * p.w;
            }
            out[CONT_BASE + (size_t)gtok * 50 + o] = acc;
        } else if (o < 60) {
            const int o2 = o - 50;
            float acc = bbs[o2];
            const float4* wp = (const float4*)&Wbs[o2 * 268];
            const float4* pp = (const float4*)&pred[tt * 268];
#pragma unroll 11
            for (int q = 0; q < 66; q++) {
                float4 w = wp[q], p = pp[q];
                acc += w.x * p.x + w.y * p.y + w.z * p.z + w.w * p.w;
            }
            out[BIN_BASE + (size_t)gtok * 10 + o2] = 1.0f / (1.0f + __expf(-acc));
        } else {
            const int o3 = o - 60;
            float acc = bas[o3];
            const float4* wp = (const float4*)&Was[o3 * 256];
            const float4* pp = (const float4*)&a1s[tt * 256];
#pragma unroll 16
            for (int q = 0; q < 64; q++) {
                float4 w = wp[q], p = pp[q];
                acc += w.x * p.x + w.y * p.y + w.z * p.z + w.w * p.w;
            }
            out[ACT_BASE + (size_t)gtok * 8 + o3] = acc;
        }
    }
}

// ---------------------------------------------------------------------------
extern "C" void kernel_launch(void* const* d_in, const int* in_sizes, int n_in,
                              void* d_out, int out_size) {
    const float* x    = (const float*)d_in[0];
    const float* Wih  = (const float*)d_in[1];
    const float* Whh  = (const float*)d_in[2];
    const float* bih  = (const float*)d_in[3];
    const float* bhh  = (const float*)d_in[4];
    const float* Wafc = (const float*)d_in[5];
    const float* bafc = (const float*)d_in[6];
    const float* Wao  = (const float*)d_in[7];
    const float* bao  = (const float*)d_in[8];
    const float* Wc   = (const float*)d_in[9];
    const float* bc   = (const float*)d_in[10];
    const float* Wb   = (const float*)d_in[11];
    const float* bb   = (const float*)d_in[12];
    float* out = (float*)d_out;

    cudaFuncSetAttribute(kB,  cudaFuncAttributeMaxDynamicSharedMemorySize, SMEM_B);
    cudaFuncSetAttribute(kC1, cudaFuncAttributeMaxDynamicSharedMemorySize, SMEM_C1);
    cudaFuncSetAttribute(kC2, cudaFuncAttributeMaxDynamicSharedMemorySize, SMEM_C2);

    k_init<<<1, 32>>>();
    kA<<<dim3(4, 32, 128), 256>>>(x, Wih, bih, bhh);
    kB<<<128, 256, SMEM_B>>>(Whh);
    kC1<<<4096, 256, SMEM_C1>>>(Wafc, bafc);
    kC2<<<4096, 256, SMEM_C2>>>(x, Wao, bao, Wc, bc, Wb, bb, out);
}